// round 13
// baseline (speedup 1.0000x reference)
#include <cuda_runtime.h>
#include <cstdint>
#include <cstddef>

#define TT 256
#define BB 64
#define DD 512
#define HH 1024
#define GG 4096
#define NBLK 128
#define EPSB 1e-5f
#define HROW 144   // words per staged k-row; MUST be %4==0 (16B-aligned rows for LDS.128)

// ---------------- scratch (device globals: no allocation allowed) ----------------
__device__ float g_xw[(size_t)TT * BB * GG];   // 256 MB: raw x@w_ih
__device__ float g_y0[(size_t)TT * BB * HH];   // 64 MB: layer-0 output (h history for layer 0)
__device__ float g_hzero[BB * HH];             // zeros (t=0 h source)
__device__ int   g_flag[NBLK * 32];            // per-producer progress flags, 128B stride

// ---------------- packed f32x2 + fast-math helpers ----------------
__device__ __forceinline__ void fma2(unsigned long long& d, unsigned long long a, unsigned long long b) {
    asm("fma.rn.f32x2 %0, %1, %2, %3;" : "=l"(d) : "l"(a), "l"(b), "l"(d));
}
__device__ __forceinline__ float2 upk2(unsigned long long v) {
    float lo, hi;
    asm("mov.b64 {%0, %1}, %2;" : "=f"(lo), "=f"(hi) : "l"(v));
    return make_float2(lo, hi);
}
__device__ __forceinline__ float tanh_f(float x) {
    float r;
    asm("tanh.approx.f32 %0, %1;" : "=f"(r) : "f"(x));
    return r;
}
__device__ __forceinline__ float sigf(float x) { return fmaf(tanh_f(0.5f * x), 0.5f, 0.5f); }
__device__ __forceinline__ int ldacq(const int* p) {
    int v;
    asm volatile("ld.acquire.gpu.global.b32 %0, [%1];" : "=r"(v) : "l"(p) : "memory");
    return v;
}

// ---------------- input GEMM: g_xw(raw) = A(16384 x K) @ W(K x 4096) ----------------
__global__ __launch_bounds__(256) void gemm_xw_kernel(const float* __restrict__ A,
                                                      const float* __restrict__ W, int K) {
    __shared__ __align__(16) float As[2][8][132];
    __shared__ __align__(16) float Bd[2][8][260];
    const int n0 = blockIdx.x * 128, m0 = blockIdx.y * 128;
    const int tid = threadIdx.x;
    const int rg = tid & 15, cg = tid >> 4;
    const int r0 = rg * 8, c0 = cg * 8;
    const int ar = tid >> 1, ak = (tid & 1) * 4;
    const int bk = tid >> 5, bc = (tid & 31) * 4;
    const float* pA = A + (size_t)(m0 + ar) * K + ak;
    const float* pB = W + (size_t)bk * GG + n0 + bc;

    unsigned long long acc[4][8] = {};

    float4 va = *(const float4*)pA;
    float4 vb = *(const float4*)pB;
    As[0][ak + 0][ar] = va.x; As[0][ak + 1][ar] = va.y;
    As[0][ak + 2][ar] = va.z; As[0][ak + 3][ar] = va.w;
    *(float2*)&Bd[0][bk][2 * (bc + 0)] = make_float2(vb.x, vb.x);
    *(float2*)&Bd[0][bk][2 * (bc + 1)] = make_float2(vb.y, vb.y);
    *(float2*)&Bd[0][bk][2 * (bc + 2)] = make_float2(vb.z, vb.z);
    *(float2*)&Bd[0][bk][2 * (bc + 3)] = make_float2(vb.w, vb.w);
    __syncthreads();

    int buf = 0;
    for (int kc = 8; kc <= K; kc += 8) {
        const bool more = (kc < K);
        if (more) {
            va = *(const float4*)(pA + kc);
            vb = *(const float4*)(pB + (size_t)kc * GG);
        }
#pragma unroll
        for (int k = 0; k < 8; k++) {
            ulonglong2 a0 = *(const ulonglong2*)&As[buf][k][r0];
            ulonglong2 a1 = *(const ulonglong2*)&As[buf][k][r0 + 4];
            ulonglong2 w01 = *(const ulonglong2*)&Bd[buf][k][2 * c0];
            ulonglong2 w23 = *(const ulonglong2*)&Bd[buf][k][2 * c0 + 4];
            ulonglong2 w45 = *(const ulonglong2*)&Bd[buf][k][2 * c0 + 8];
            ulonglong2 w67 = *(const ulonglong2*)&Bd[buf][k][2 * c0 + 12];
            unsigned long long avp[4] = {a0.x, a0.y, a1.x, a1.y};
            unsigned long long wr[8] = {w01.x, w01.y, w23.x, w23.y, w45.x, w45.y, w67.x, w67.y};
#pragma unroll
            for (int p = 0; p < 4; p++)
#pragma unroll
                for (int c = 0; c < 8; c++) fma2(acc[p][c], avp[p], wr[c]);
        }
        if (more) {
            int nb = buf ^ 1;
            As[nb][ak + 0][ar] = va.x; As[nb][ak + 1][ar] = va.y;
            As[nb][ak + 2][ar] = va.z; As[nb][ak + 3][ar] = va.w;
            *(float2*)&Bd[nb][bk][2 * (bc + 0)] = make_float2(vb.x, vb.x);
            *(float2*)&Bd[nb][bk][2 * (bc + 1)] = make_float2(vb.y, vb.y);
            *(float2*)&Bd[nb][bk][2 * (bc + 2)] = make_float2(vb.z, vb.z);
            *(float2*)&Bd[nb][bk][2 * (bc + 3)] = make_float2(vb.w, vb.w);
            __syncthreads();
            buf = nb;
        }
    }
#pragma unroll
    for (int p = 0; p < 4; p++) {
        float2 u[8];
#pragma unroll
        for (int c = 0; c < 8; c++) u[c] = upk2(acc[p][c]);
        float* o0 = &g_xw[(size_t)(m0 + r0 + 2 * p) * GG + n0 + c0];
        float* o1 = o0 + GG;
        *(float4*)o0       = make_float4(u[0].x, u[1].x, u[2].x, u[3].x);
        *(float4*)(o0 + 4) = make_float4(u[4].x, u[5].x, u[6].x, u[7].x);
        *(float4*)o1       = make_float4(u[0].y, u[1].y, u[2].y, u[3].y);
        *(float4*)(o1 + 4) = make_float4(u[4].y, u[5].y, u[6].y, u[7].y);
    }
}

// ---------------- init: zero flag array + zero-h buffer ----------------
__global__ void init_kernel() {
    const int i = blockIdx.x * 256 + threadIdx.x;
    if (i < BB * HH) g_hzero[i] = 0.f;
    if (i < NBLK * 32) g_flag[i] = 0;
}

// ---------------- epilogue smem layout (aliases the h staging region) ----------------
struct SR {
    float Cs[4][64][34];    // 8-way k-split partials, pair-summed into planes 0..3
    float Xs[64][36];
    float redA[16][32], redB[16][32], redC[16][32], redD[16][32];
    float scH[32], shH[32], scX[32], shX[32];
    float c1s[64][9], oss[64][9];
    float scc[8], shc[8];
};

// skewed dup-h word index for batch row b
__device__ __forceinline__ int hword(int b) {
    return 8 * (b >> 2) + 4 * (b >> 4) + 2 * (b & 3);
}

// ---------------- persistent recurrence kernel: all 256 steps of one layer ----------------
// 128 blocks x 512 threads (16 warps/SM, 4/SMSP). Block blk owns gate cols
// {g*1024 + blk*8 + j}. Weights smem-resident. Flag dataflow (no grid barrier):
// y IS the masked h; producers release per-block flags; consumers gate each 32-k
// staging chunk on producer flags prefetched one chunk ahead.
// GEMM is K-split 8 ways: octet o (2 warps) covers k = o*4+kk of each 32-chunk.
__global__ __launch_bounds__(512) void lstm_persist_kernel(
    const float* __restrict__ whh,
    const float* __restrict__ ghh, const float* __restrict__ bthh,
    const float* __restrict__ gih, const float* __restrict__ btih,
    const float* __restrict__ bias,
    const float* __restrict__ gcb, const float* __restrict__ btcb,
    const int* __restrict__ length,
    float* __restrict__ y_out, float* __restrict__ hn_out, float* __restrict__ cn_out) {
    extern __shared__ float smem[];
    float* wsm = smem;                                       // [1024][32]
    float (*hst)[32][HROW] = (float (*)[32][HROW])(smem + HH * 32);
    SR* sr = (SR*)(smem + HH * 32);

    const int blk = blockIdx.x, tid = threadIdx.x;

    // ---- one-time: load this block's 32 weight cols (1024x32 = 128 KB) ----
    for (int idx = tid; idx < HH * 32; idx += 512) {
        int c = idx & 31, k = idx >> 5;
        wsm[k * 32 + c] = whh[(size_t)k * GG + (c >> 3) * HH + blk * 8 + (c & 7)];
    }

    // epilogue element mapping: f = tid -> b = f>>3, j/sub = f&7 (512 = 64x8)
    float cr = 0.f, hr = 0.f;
    const int lenr = length[tid >> 3];

    // GEMM lane mapping: octet = 2 warps, lane tile 4 rows x 8 cols
    const int oct = tid >> 6, tq = tid & 63;
    const int rg = tq & 15, cg = tq >> 4;
    const int RB = 8 * rg + 4 * (rg >> 2);

    // staging slot: thread covers h row sb, k-quad kq of each 32-chunk
    const int sb = tid >> 3, kq = (tid & 7) * 4;
    const int fq = (kq >> 3) * 32;               // flag sub-offset within chunk group

    int fv = __ldcg(&g_flag[fq]);

    __syncthreads();

    for (int t = 0; t < TT; t++) {
        const float* hsrc = t ? (y_out + (size_t)(t - 1) * BB * HH) : g_hzero;

        // ---- prefetch xw slice (consumed in the epilogue) ----
        float4 xwv;
        {
            int b = tid >> 3, sub = tid & 7;
            int gate = sub >> 1, jj = (sub & 1) * 4;
            xwv = __ldg((const float4*)&g_xw[((size_t)t * BB + b) * GG + gate * HH + blk * 8 + jj]);
        }

        // ---- GEMM: C(64x32) = h(64x1024) @ wsm(1024x32), K-split 8, chunked 32 ----
        unsigned long long acc[4][4] = {};

        // chunk 0: gate on flag (prefetched), load, stage; prefetch flag for chunk 32
        while (fv < t) fv = ldacq(&g_flag[fq]);
        float4 sh = __ldcv((const float4*)&hsrc[sb * HH + kq]);
        fv = __ldcg(&g_flag[128 + fq]);
        {
            int w = hword(sb);
            *(float2*)&hst[0][kq + 0][w] = make_float2(sh.x, sh.x);
            *(float2*)&hst[0][kq + 1][w] = make_float2(sh.y, sh.y);
            *(float2*)&hst[0][kq + 2][w] = make_float2(sh.z, sh.z);
            *(float2*)&hst[0][kq + 3][w] = make_float2(sh.w, sh.w);
        }
        __syncthreads();

        int buf = 0;
        for (int kc = 32; kc <= HH; kc += 32) {
            const bool more = (kc < HH);
            if (more) {
                const int gb = (kc >> 3) * 32;
                while (fv < t) fv = ldacq(&g_flag[gb + fq]);
                sh = __ldcv((const float4*)&hsrc[sb * HH + kc + kq]);
                const int nb_ = (kc < HH - 32) ? (gb + 128) : 0;
                fv = __ldcg(&g_flag[nb_ + fq]);
            }
            const int kbase = kc - 32;
#pragma unroll
            for (int kk = 0; kk < 4; kk++) {
                int k = oct * 4 + kk;
                ulonglong2 a01 = *(const ulonglong2*)&hst[buf][k][RB];
                ulonglong2 a23 = *(const ulonglong2*)&hst[buf][k][RB + 4];
                const float* wr_ = &wsm[(kbase + k) * 32 + 8 * cg];
                ulonglong2 wlo = *(const ulonglong2*)wr_;
                ulonglong2 whi = *(const ulonglong2*)(wr_ + 4);
                unsigned long long av[4] = {a01.x, a01.y, a23.x, a23.y};
                unsigned long long wv[4] = {wlo.x, wlo.y, whi.x, whi.y};
#pragma unroll
                for (int r = 0; r < 4; r++)
#pragma unroll
                    for (int cp = 0; cp < 4; cp++) fma2(acc[r][cp], av[r], wv[cp]);
            }
            if (more) {
                int nb = buf ^ 1;
                int w = hword(sb);
                *(float2*)&hst[nb][kq + 0][w] = make_float2(sh.x, sh.x);
                *(float2*)&hst[nb][kq + 1][w] = make_float2(sh.y, sh.y);
                *(float2*)&hst[nb][kq + 2][w] = make_float2(sh.z, sh.z);
                *(float2*)&hst[nb][kq + 3][w] = make_float2(sh.w, sh.w);
                __syncthreads();
                buf = nb;
            }
        }
        __syncthreads();   // GEMM reads done; smem aliases to SR below

        // ---- phase 1: octets 0-3 store partials; everyone stores Xs ----
        if (oct < 4) {
#pragma unroll
            for (int r = 0; r < 4; r++)
#pragma unroll
                for (int cp = 0; cp < 4; cp++) {
                    float2 u = upk2(acc[r][cp]);
                    *(float2*)&sr->Cs[oct][4 * rg + r][8 * cg + 2 * cp] = u;
                }
        }
        {
            int b = tid >> 3, sub = tid & 7;
            int gate = sub >> 1, jj = (sub & 1) * 4;
            *(float4*)&sr->Xs[b][gate * 8 + jj] = xwv;
        }
        __syncthreads();

        // ---- phase 2: octets 4-7 add their partials ----
        if (oct >= 4) {
#pragma unroll
            for (int r = 0; r < 4; r++)
#pragma unroll
                for (int cp = 0; cp < 4; cp++) {
                    float2 u = upk2(acc[r][cp]);
                    float2* p = (float2*)&sr->Cs[oct - 4][4 * rg + r][8 * cg + 2 * cp];
                    float2 o = *p;
                    *p = make_float2(o.x + u.x, o.y + u.y);
                }
        }
        __syncthreads();

        // ---- BN stats over batch for hh-GEMM and ih (raw xw) columns ----
        {
            int c = tid & 31, grp = tid >> 5;   // 16 groups of 4 batch rows
            float sC = 0.f, s2C = 0.f, sX = 0.f, s2X = 0.f;
#pragma unroll
            for (int b = grp * 4; b < grp * 4 + 4; b++) {
                float v = sr->Cs[0][b][c] + sr->Cs[1][b][c] + sr->Cs[2][b][c] + sr->Cs[3][b][c];
                sr->Cs[0][b][c] = v;
                sC += v; s2C += v * v;
                float u = sr->Xs[b][c];
                sX += u; s2X += u * u;
            }
            sr->redA[grp][c] = sC; sr->redB[grp][c] = s2C;
            sr->redC[grp][c] = sX; sr->redD[grp][c] = s2X;
        }
        __syncthreads();
        if (tid < 32) {
            float sC = 0.f, s2C = 0.f, sX = 0.f, s2X = 0.f;
#pragma unroll
            for (int g = 0; g < 16; g++) {
                sC += sr->redA[g][tid]; s2C += sr->redB[g][tid];
                sX += sr->redC[g][tid]; s2X += sr->redD[g][tid];
            }
            int col = (tid >> 3) * HH + blk * 8 + (tid & 7);
            float muC = sC * (1.f / 64.f);
            float varC = fmaxf(s2C * (1.f / 64.f) - muC * muC, 0.f);
            float a = ghh[col] * rsqrtf(varC + EPSB);
            sr->scH[tid] = a; sr->shH[tid] = bthh[col] - muC * a;
            float muX = sX * (1.f / 64.f);
            float varX = fmaxf(s2X * (1.f / 64.f) - muX * muX, 0.f);
            float e = gih[col] * rsqrtf(varX + EPSB);
            sr->scX[tid] = e; sr->shX[tid] = btih[col] + bias[col] - muX * e;
        }
        __syncthreads();

        // ---- gates + cell update (c from registers; 1 element/thread) ----
        {
            int b = tid >> 3, j = tid & 7;
            float pre[4];
#pragma unroll
            for (int g = 0; g < 4; g++) {
                int c = g * 8 + j;
                pre[g] = sr->Cs[0][b][c] * sr->scH[c] + sr->shH[c]
                       + sr->Xs[b][c] * sr->scX[c] + sr->shX[c];
            }
            float c1 = sigf(pre[0]) * cr + sigf(pre[1]) * tanh_f(pre[3]);
            sr->c1s[b][j] = c1;
            sr->oss[b][j] = sigf(pre[2]);
        }
        __syncthreads();

        // ---- BN stats over batch for the 8 cell columns ----
        if (tid < 64) {
            int j = tid & 7, grp = tid >> 3;
            float s = 0.f, s2 = 0.f;
#pragma unroll
            for (int b = grp * 8; b < grp * 8 + 8; b++) {
                float v = sr->c1s[b][j]; s += v; s2 += v * v;
            }
            sr->redA[grp][j] = s; sr->redB[grp][j] = s2;
        }
        __syncthreads();
        if (tid < 8) {
            float s = 0.f, s2 = 0.f;
#pragma unroll
            for (int g = 0; g < 8; g++) { s += sr->redA[g][tid]; s2 += sr->redB[g][tid]; }
            float mu = s * (1.f / 64.f);
            float var = fmaxf(s2 * (1.f / 64.f) - mu * mu, 0.f);
            int hcol = blk * 8 + tid;
            float a = gcb[hcol] * rsqrtf(var + EPSB);
            sr->scc[tid] = a; sr->shc[tid] = btcb[hcol] - mu * a;
        }
        __syncthreads();

        // ---- h update with length mask; write y (= h history) + finals ----
        {
            int b = tid >> 3, j = tid & 7;
            int hcol = blk * 8 + j;
            float c1 = sr->c1s[b][j];
            float h1 = sr->oss[b][j] * tanh_f(c1 * sr->scc[j] + sr->shc[j]);
            bool m = t < lenr;
            float hn = m ? h1 : hr;
            float cn = m ? c1 : cr;
            hr = hn; cr = cn;
            y_out[((size_t)t * BB + b) * HH + hcol] = hn;
            if (t == TT - 1) {
                hn_out[b * HH + hcol] = hn;
                cn_out[b * HH + hcol] = cn;
            }
        }

        // ---- publish progress: writes visible, then release flag ----
        __threadfence();
        __syncthreads();
        if (tid == 0) {
            asm volatile("st.release.gpu.global.b32 [%0], %1;"
                         :: "l"(&g_flag[blk * 32]), "r"(t + 1) : "memory");
        }
    }
}

// ---------------- host orchestration ----------------
extern "C" void kernel_launch(void* const* d_in, const int* in_sizes, int n_in,
                              void* d_out, int out_size) {
    const float* x     = (const float*)d_in[0];
    const int* length  = (const int*)d_in[1];
    const float* w_ih0 = (const float*)d_in[2];
    const float* w_hh0 = (const float*)d_in[3];
    const float* b0    = (const float*)d_in[4];
    const float* gih0  = (const float*)d_in[5];
    const float* btih0 = (const float*)d_in[6];
    const float* ghh0  = (const float*)d_in[7];
    const float* bthh0 = (const float*)d_in[8];
    const float* gc0   = (const float*)d_in[9];
    const float* btc0  = (const float*)d_in[10];
    const float* w_ih1 = (const float*)d_in[11];
    const float* w_hh1 = (const float*)d_in[12];
    const float* b1    = (const float*)d_in[13];
    const float* gih1  = (const float*)d_in[14];
    const float* btih1 = (const float*)d_in[15];
    const float* ghh1  = (const float*)d_in[16];
    const float* bthh1 = (const float*)d_in[17];
    const float* gc1   = (const float*)d_in[18];
    const float* btc1  = (const float*)d_in[19];

    float* out = (float*)d_out;
    float* y1 = out;
    float* hn = out + (size_t)TT * BB * HH;
    float* cn = hn + 2 * BB * HH;

    float* p_y0 = nullptr;
    cudaGetSymbolAddress((void**)&p_y0, g_y0);

    // dynamic smem: 128 KB weights + max(h staging, SR) region
    const size_t smreg = (size_t)2 * 32 * HROW * sizeof(float);
    const size_t srsz = sizeof(SR);
    const size_t smbytes = (size_t)HH * 32 * sizeof(float) + (smreg > srsz ? smreg : srsz);
    cudaFuncSetAttribute(lstm_persist_kernel,
                         cudaFuncAttributeMaxDynamicSharedMemorySize, (int)smbytes);

    const dim3 ggrid(GG / 128, (TT * BB) / 128);
    const int initgrid = (BB * HH + 255) / 256;

    // ---- layer 0 ----
    gemm_xw_kernel<<<ggrid, 256>>>(x, w_ih0, DD);
    init_kernel<<<initgrid, 256>>>();
    lstm_persist_kernel<<<NBLK, 512, smbytes>>>(w_hh0, ghh0, bthh0, gih0, btih0, b0,
                                                gc0, btc0, length, p_y0, hn, cn);

    // ---- layer 1 ----
    gemm_xw_kernel<<<ggrid, 256>>>(p_y0, w_ih1, HH);
    init_kernel<<<initgrid, 256>>>();
    lstm_persist_kernel<<<NBLK, 512, smbytes>>>(w_hh1, ghh1, bthh1, gih1, btih1, b1,
                                                gc1, btc1, length, y1, hn + BB * HH, cn + BB * HH);
}

// round 14
// speedup vs baseline: 1.4301x; 1.4301x over previous
#include <cuda_runtime.h>
#include <cstdint>
#include <cstddef>

#define TT 256
#define BB 64
#define DD 512
#define HH 1024
#define GG 4096
#define EPSB 1e-5f

// ---------------- scratch (device globals: no allocation allowed) ----------------
__device__ float g_xw[(size_t)TT * BB * GG];   // 256 MB: raw x@w_ih (BN folded into step)
__device__ float g_y0[(size_t)TT * BB * HH];   // 64 MB: layer-0 output
__device__ float g_h[2][BB * HH];              // ping-pong hidden state
__device__ float g_c[BB * HH];                 // cell state (in-place)
__device__ float g_wpack[HH * GG];             // per-block packed recurrent weights

// ---------------- packed f32x2 + fast-math helpers ----------------
__device__ __forceinline__ unsigned long long pk2(float lo, float hi) {
    unsigned long long r;
    asm("mov.b64 %0, {%1, %2};" : "=l"(r) : "f"(lo), "f"(hi));
    return r;
}
__device__ __forceinline__ void fma2(unsigned long long& d, unsigned long long a, unsigned long long b) {
    asm("fma.rn.f32x2 %0, %1, %2, %3;" : "=l"(d) : "l"(a), "l"(b), "l"(d));
}
__device__ __forceinline__ float2 upk2(unsigned long long v) {
    float lo, hi;
    asm("mov.b64 {%0, %1}, %2;" : "=f"(lo), "=f"(hi) : "l"(v));
    return make_float2(lo, hi);
}
__device__ __forceinline__ float tanh_f(float x) {
    float r;
    asm("tanh.approx.f32 %0, %1;" : "=f"(r) : "f"(x));
    return r;
}
__device__ __forceinline__ float sigf(float x) { return fmaf(tanh_f(0.5f * x), 0.5f, 0.5f); }

// 2 row-pairs (packed) x 4 cols micro-tile: 16 MACs in 8 fma2 + 4 packs
__device__ __forceinline__ void mma16(unsigned long long acc[2][4], ulonglong2 av, float4 wv) {
    unsigned long long w0 = pk2(wv.x, wv.x), w1 = pk2(wv.y, wv.y),
                       w2 = pk2(wv.z, wv.z), w3 = pk2(wv.w, wv.w);
    fma2(acc[0][0], av.x, w0); fma2(acc[1][0], av.y, w0);
    fma2(acc[0][1], av.x, w1); fma2(acc[1][1], av.y, w1);
    fma2(acc[0][2], av.x, w2); fma2(acc[1][2], av.y, w2);
    fma2(acc[0][3], av.x, w3); fma2(acc[1][3], av.y, w3);
}

// ---------------- input GEMM: g_xw(raw) = A(16384 x K) @ W(K x 4096) ----------------
// 128x128 block tile, 256 threads, lane tile 8x8 (proven 47% fma).
__global__ __launch_bounds__(256) void gemm_xw_kernel(const float* __restrict__ A,
                                                      const float* __restrict__ W, int K) {
    __shared__ __align__(16) float As[2][8][132];
    __shared__ __align__(16) float Bd[2][8][260];
    const int n0 = blockIdx.x * 128, m0 = blockIdx.y * 128;
    const int tid = threadIdx.x;
    const int rg = tid & 15, cg = tid >> 4;
    const int r0 = rg * 8, c0 = cg * 8;
    const int ar = tid >> 1, ak = (tid & 1) * 4;
    const int bk = tid >> 5, bc = (tid & 31) * 4;
    const float* pA = A + (size_t)(m0 + ar) * K + ak;
    const float* pB = W + (size_t)bk * GG + n0 + bc;

    unsigned long long acc[4][8] = {};

    float4 va = *(const float4*)pA;
    float4 vb = *(const float4*)pB;
    As[0][ak + 0][ar] = va.x; As[0][ak + 1][ar] = va.y;
    As[0][ak + 2][ar] = va.z; As[0][ak + 3][ar] = va.w;
    *(float2*)&Bd[0][bk][2 * (bc + 0)] = make_float2(vb.x, vb.x);
    *(float2*)&Bd[0][bk][2 * (bc + 1)] = make_float2(vb.y, vb.y);
    *(float2*)&Bd[0][bk][2 * (bc + 2)] = make_float2(vb.z, vb.z);
    *(float2*)&Bd[0][bk][2 * (bc + 3)] = make_float2(vb.w, vb.w);
    __syncthreads();

    int buf = 0;
    for (int kc = 8; kc <= K; kc += 8) {
        const bool more = (kc < K);
        if (more) {
            va = *(const float4*)(pA + kc);
            vb = *(const float4*)(pB + (size_t)kc * GG);
        }
#pragma unroll
        for (int k = 0; k < 8; k++) {
            ulonglong2 a0 = *(const ulonglong2*)&As[buf][k][r0];
            ulonglong2 a1 = *(const ulonglong2*)&As[buf][k][r0 + 4];
            ulonglong2 w01 = *(const ulonglong2*)&Bd[buf][k][2 * c0];
            ulonglong2 w23 = *(const ulonglong2*)&Bd[buf][k][2 * c0 + 4];
            ulonglong2 w45 = *(const ulonglong2*)&Bd[buf][k][2 * c0 + 8];
            ulonglong2 w67 = *(const ulonglong2*)&Bd[buf][k][2 * c0 + 12];
            unsigned long long avp[4] = {a0.x, a0.y, a1.x, a1.y};
            unsigned long long wr[8] = {w01.x, w01.y, w23.x, w23.y, w45.x, w45.y, w67.x, w67.y};
#pragma unroll
            for (int p = 0; p < 4; p++)
#pragma unroll
                for (int c = 0; c < 8; c++) fma2(acc[p][c], avp[p], wr[c]);
        }
        if (more) {
            int nb = buf ^ 1;
            As[nb][ak + 0][ar] = va.x; As[nb][ak + 1][ar] = va.y;
            As[nb][ak + 2][ar] = va.z; As[nb][ak + 3][ar] = va.w;
            *(float2*)&Bd[nb][bk][2 * (bc + 0)] = make_float2(vb.x, vb.x);
            *(float2*)&Bd[nb][bk][2 * (bc + 1)] = make_float2(vb.y, vb.y);
            *(float2*)&Bd[nb][bk][2 * (bc + 2)] = make_float2(vb.z, vb.z);
            *(float2*)&Bd[nb][bk][2 * (bc + 3)] = make_float2(vb.w, vb.w);
            __syncthreads();
            buf = nb;
        }
    }
#pragma unroll
    for (int p = 0; p < 4; p++) {
        float2 u[8];
#pragma unroll
        for (int c = 0; c < 8; c++) u[c] = upk2(acc[p][c]);
        float* o0 = &g_xw[(size_t)(m0 + r0 + 2 * p) * GG + n0 + c0];
        float* o1 = o0 + GG;
        *(float4*)o0       = make_float4(u[0].x, u[1].x, u[2].x, u[3].x);
        *(float4*)(o0 + 4) = make_float4(u[4].x, u[5].x, u[6].x, u[7].x);
        *(float4*)o1       = make_float4(u[0].y, u[1].y, u[2].y, u[3].y);
        *(float4*)(o1 + 4) = make_float4(u[4].y, u[5].y, u[6].y, u[7].y);
    }
}

// ---------------- pack w_hh so block blk owns gate cols {g*H + blk*8 + j} ----------------
__global__ void pack_w_kernel(const float* __restrict__ w) {
    const int idx = blockIdx.x * 256 + threadIdx.x;  // < HH*GG
    const int c = idx & 31;
    const int k = (idx >> 5) & (HH - 1);
    const int blk = idx >> 15;
    g_wpack[idx] = w[(size_t)k * GG + (c >> 3) * HH + blk * 8 + (c & 7)];
}

__global__ void init_hc_kernel() {
    const int i = blockIdx.x * 256 + threadIdx.x;
    if (i < BB * HH) { g_h[0][i] = 0.f; g_h[1][i] = 0.f; g_c[i] = 0.f; }
}

__global__ void copy_hc_kernel(float* __restrict__ oh, float* __restrict__ oc) {
    const int i = blockIdx.x * 256 + threadIdx.x;
    if (i < BB * HH) { oh[i] = g_h[0][i]; oc[i] = g_c[i]; }
}

// ---------------- one LSTM timestep (R3 structure + folded BN-ih + MUFU) ----------------
// 128 blocks x 128 threads; block blk owns h-cols [blk*8, blk*8+8) and gate cols
// {g*1024 + blk*8 + j}. All BN stats (hh, ih, cell) are block-local.
__global__ __launch_bounds__(128) void lstm_step_kernel(
    int t, int par,
    const float* __restrict__ ghh, const float* __restrict__ bthh,
    const float* __restrict__ gih, const float* __restrict__ btih,
    const float* __restrict__ bias,
    const float* __restrict__ gcb, const float* __restrict__ btcb,
    const int* __restrict__ length, float* __restrict__ y_out) {
    __shared__ __align__(16) float hsT[2][32][68];  // [k][b], transposed
    __shared__ __align__(16) float ws[2][32][36];   // [k][c]
    __shared__ __align__(16) float Cs[64][36];      // h@w_hh result (b, gate-local c)
    __shared__ __align__(16) float Xs[64][36];      // raw x@w_ih slice
    __shared__ float redA[8][32], redB[8][32], redC[8][32], redD[8][32];
    __shared__ float scH[32], shH[32], scX[32], shX[32];
    __shared__ float c1s[64][9], oss[64][9];
    __shared__ float scc[8], shc[8];

    const int blk = blockIdx.x, tid = threadIdx.x;
    const float* hin = g_h[par];
    float* hout = g_h[par ^ 1];
    const float* wp = g_wpack + (size_t)blk * (HH * 32);

    // ---- early prefetch: xw slice + cell state + lengths (latency hidden under GEMM) ----
    float4 xwv[4]; float coldr[4]; int lenr[4];
#pragma unroll
    for (int i = 0; i < 4; i++) {
        int f = tid + i * 128;                 // < 512: b = f>>3, sub = f&7
        int b = f >> 3, sub = f & 7;
        int gate = sub >> 1, jj = (sub & 1) * 4;
        xwv[i] = __ldg((const float4*)&g_xw[((size_t)t * BB + b) * GG + gate * HH + blk * 8 + jj]);
        coldr[i] = g_c[b * HH + blk * 8 + sub];
        lenr[i] = length[b];
    }

    const int rt = tid & 15, ct = tid >> 4;
    const int r0 = rt * 4, c0 = ct * 4;
    unsigned long long acc[2][4] = {};

    // ---- GEMM: Cs(64x32) = hin(64x1024) @ wp(1024x32), chunked K=32, double-buffered ----
    float4 ph[4], pw[2];
#pragma unroll
    for (int i = 0; i < 4; i++) {
        int idx = tid + i * 128;
        ph[i] = *(const float4*)&hin[(idx >> 3) * HH + (idx & 7) * 4];
    }
#pragma unroll
    for (int i = 0; i < 2; i++) {
        int idx = tid + i * 128;
        pw[i] = *(const float4*)&wp[(idx >> 3) * 32 + (idx & 7) * 4];
    }
#pragma unroll
    for (int i = 0; i < 4; i++) {
        int idx = tid + i * 128;
        int b = idx >> 3, kq = (idx & 7) * 4;
        hsT[0][kq + 0][b] = ph[i].x; hsT[0][kq + 1][b] = ph[i].y;
        hsT[0][kq + 2][b] = ph[i].z; hsT[0][kq + 3][b] = ph[i].w;
    }
#pragma unroll
    for (int i = 0; i < 2; i++) {
        int idx = tid + i * 128;
        *(float4*)&ws[0][idx >> 3][(idx & 7) * 4] = pw[i];
    }
    __syncthreads();

    int buf = 0;
    for (int kc = 32; kc <= HH; kc += 32) {
        const bool more = (kc < HH);
        if (more) {
#pragma unroll
            for (int i = 0; i < 4; i++) {
                int idx = tid + i * 128;
                ph[i] = *(const float4*)&hin[(idx >> 3) * HH + kc + (idx & 7) * 4];
            }
#pragma unroll
            for (int i = 0; i < 2; i++) {
                int idx = tid + i * 128;
                pw[i] = *(const float4*)&wp[(kc + (idx >> 3)) * 32 + (idx & 7) * 4];
            }
        }
#pragma unroll
        for (int k = 0; k < 32; k++) {
            ulonglong2 av = *(const ulonglong2*)&hsT[buf][k][r0];
            float4 wv = *(const float4*)&ws[buf][k][c0];
            mma16(acc, av, wv);
        }
        if (more) {
            int nb = buf ^ 1;
#pragma unroll
            for (int i = 0; i < 4; i++) {
                int idx = tid + i * 128;
                int b = idx >> 3, kq = (idx & 7) * 4;
                hsT[nb][kq + 0][b] = ph[i].x; hsT[nb][kq + 1][b] = ph[i].y;
                hsT[nb][kq + 2][b] = ph[i].z; hsT[nb][kq + 3][b] = ph[i].w;
            }
#pragma unroll
            for (int i = 0; i < 2; i++) {
                int idx = tid + i * 128;
                *(float4*)&ws[nb][idx >> 3][(idx & 7) * 4] = pw[i];
            }
            __syncthreads();
            buf = nb;
        }
    }
    __syncthreads();

    // ---- store GEMM result + xw slice to smem ----
#pragma unroll
    for (int rp = 0; rp < 2; rp++) {
        float2 u0 = upk2(acc[rp][0]), u1 = upk2(acc[rp][1]),
               u2 = upk2(acc[rp][2]), u3 = upk2(acc[rp][3]);
        *(float4*)&Cs[r0 + 2 * rp][c0]     = make_float4(u0.x, u1.x, u2.x, u3.x);
        *(float4*)&Cs[r0 + 2 * rp + 1][c0] = make_float4(u0.y, u1.y, u2.y, u3.y);
    }
#pragma unroll
    for (int i = 0; i < 4; i++) {
        int f = tid + i * 128;
        int b = f >> 3, sub = f & 7;
        int gate = sub >> 1, jj = (sub & 1) * 4;
        *(float4*)&Xs[b][gate * 8 + jj] = xwv[i];
    }
    __syncthreads();

    // ---- BN stats over batch for hh-GEMM and ih (raw xw) columns ----
    {
        int c = tid & 31, q = tid >> 5;
        float sC = 0.f, s2C = 0.f, sX = 0.f, s2X = 0.f;
#pragma unroll
        for (int b = q * 16; b < q * 16 + 16; b++) {
            float v = Cs[b][c]; sC += v; s2C += v * v;
            float u = Xs[b][c]; sX += u; s2X += u * u;
        }
        redA[q][c] = sC; redB[q][c] = s2C; redC[q][c] = sX; redD[q][c] = s2X;
    }
    __syncthreads();
    if (tid < 32) {
        float sC = redA[0][tid] + redA[1][tid] + redA[2][tid] + redA[3][tid];
        float s2C = redB[0][tid] + redB[1][tid] + redB[2][tid] + redB[3][tid];
        float sX = redC[0][tid] + redC[1][tid] + redC[2][tid] + redC[3][tid];
        float s2X = redD[0][tid] + redD[1][tid] + redD[2][tid] + redD[3][tid];
        int col = (tid >> 3) * HH + blk * 8 + (tid & 7);
        float muC = sC * (1.f / 64.f);
        float varC = fmaxf(s2C * (1.f / 64.f) - muC * muC, 0.f);
        float a = ghh[col] * rsqrtf(varC + EPSB);
        scH[tid] = a; shH[tid] = bthh[col] - muC * a;
        float muX = sX * (1.f / 64.f);
        float varX = fmaxf(s2X * (1.f / 64.f) - muX * muX, 0.f);
        float e = gih[col] * rsqrtf(varX + EPSB);
        scX[tid] = e; shX[tid] = btih[col] + bias[col] - muX * e;
    }
    __syncthreads();

    // ---- gates + cell update ----
#pragma unroll
    for (int i = 0; i < 4; i++) {
        int f = tid + i * 128;
        int b = f >> 3, j = f & 7;
        float pre[4];
#pragma unroll
        for (int g = 0; g < 4; g++) {
            int c = g * 8 + j;
            pre[g] = Cs[b][c] * scH[c] + shH[c] + Xs[b][c] * scX[c] + shX[c];
        }
        float c1 = sigf(pre[0]) * coldr[i] + sigf(pre[1]) * tanh_f(pre[3]);
        c1s[b][j] = c1;
        oss[b][j] = sigf(pre[2]);
    }
    __syncthreads();

    // ---- BN stats over batch for the 8 cell columns ----
    if (tid < 64) {
        int j = tid & 7, q = tid >> 3;
        float s = 0.f, s2 = 0.f;
#pragma unroll
        for (int b = q * 8; b < q * 8 + 8; b++) { float v = c1s[b][j]; s += v; s2 += v * v; }
        redA[q][j] = s; redB[q][j] = s2;
    }
    __syncthreads();
    if (tid < 8) {
        float s = 0.f, s2 = 0.f;
#pragma unroll
        for (int q = 0; q < 8; q++) { s += redA[q][tid]; s2 += redB[q][tid]; }
        float mu = s * (1.f / 64.f);
        float var = fmaxf(s2 * (1.f / 64.f) - mu * mu, 0.f);
        int hcol = blk * 8 + tid;
        float a = gcb[hcol] * rsqrtf(var + EPSB);
        scc[tid] = a; shc[tid] = btcb[hcol] - mu * a;
    }
    __syncthreads();

    // ---- h update with length mask; write h, c, y ----
#pragma unroll
    for (int i = 0; i < 4; i++) {
        int f = tid + i * 128;
        int b = f >> 3, j = f & 7;
        int hcol = blk * 8 + j;
        float c1 = c1s[b][j];
        float h1 = oss[b][j] * tanh_f(c1 * scc[j] + shc[j]);
        bool m = t < lenr[i];
        float hold = hin[b * HH + hcol];
        float hn = m ? h1 : hold;
        float cn = m ? c1 : coldr[i];
        hout[b * HH + hcol] = hn;
        g_c[b * HH + hcol] = cn;
        y_out[((size_t)t * BB + b) * HH + hcol] = hn;
    }
}

// ---------------- host orchestration ----------------
extern "C" void kernel_launch(void* const* d_in, const int* in_sizes, int n_in,
                              void* d_out, int out_size) {
    const float* x     = (const float*)d_in[0];
    const int* length  = (const int*)d_in[1];
    const float* w_ih0 = (const float*)d_in[2];
    const float* w_hh0 = (const float*)d_in[3];
    const float* b0    = (const float*)d_in[4];
    const float* gih0  = (const float*)d_in[5];
    const float* btih0 = (const float*)d_in[6];
    const float* ghh0  = (const float*)d_in[7];
    const float* bthh0 = (const float*)d_in[8];
    const float* gc0   = (const float*)d_in[9];
    const float* btc0  = (const float*)d_in[10];
    const float* w_ih1 = (const float*)d_in[11];
    const float* w_hh1 = (const float*)d_in[12];
    const float* b1    = (const float*)d_in[13];
    const float* gih1  = (const float*)d_in[14];
    const float* btih1 = (const float*)d_in[15];
    const float* ghh1  = (const float*)d_in[16];
    const float* bthh1 = (const float*)d_in[17];
    const float* gc1   = (const float*)d_in[18];
    const float* btc1  = (const float*)d_in[19];

    float* out = (float*)d_out;
    float* y1 = out;
    float* hn = out + (size_t)TT * BB * HH;
    float* cn = hn + 2 * BB * HH;

    float* p_y0 = nullptr;
    cudaGetSymbolAddress((void**)&p_y0, g_y0);

    const dim3 ggrid(GG / 128, (TT * BB) / 128);
    const int hcgrid = (BB * HH) / 256;

    // ---- layer 0 ----
    gemm_xw_kernel<<<ggrid, 256>>>(x, w_ih0, DD);
    pack_w_kernel<<<(HH * GG) / 256, 256>>>(w_hh0);
    init_hc_kernel<<<hcgrid, 256>>>();
    for (int t = 0; t < TT; t++)
        lstm_step_kernel<<<128, 128>>>(t, t & 1, ghh0, bthh0, gih0, btih0, b0,
                                       gc0, btc0, length, p_y0);
    copy_hc_kernel<<<hcgrid, 256>>>(hn, cn);

    // ---- layer 1 ----
    gemm_xw_kernel<<<ggrid, 256>>>(p_y0, w_ih1, HH);
    pack_w_kernel<<<(HH * GG) / 256, 256>>>(w_hh1);
    init_hc_kernel<<<hcgrid, 256>>>();
    for (int t = 0; t < TT; t++)
        lstm_step_kernel<<<128, 128>>>(t, t & 1, ghh1, bthh1, gih1, btih1, b1,
                                       gc1, btc1, length, y1);
    copy_hc_kernel<<<hcgrid, 256>>>(hn + BB * HH, cn + BB * HH);
}

// round 15
// speedup vs baseline: 1.4981x; 1.0475x over previous
#include <cuda_runtime.h>
#include <cstdint>
#include <cstddef>

#define TT 256
#define BB 64
#define DD 512
#define HH 1024
#define GG 4096
#define EPSB 1e-5f

// ---------------- scratch (device globals: no allocation allowed) ----------------
__device__ float g_xw[(size_t)TT * BB * GG];   // 256 MB: raw x@w_ih0 (layer-0 input GEMM)
__device__ float g_y0[(size_t)TT * BB * HH];   // 64 MB: layer-0 output (= layer-1 input)
__device__ float g_h0[2][BB * HH];             // layer-0 h ping-pong
__device__ float g_h1[2][BB * HH];             // layer-1 h ping-pong
__device__ float g_c0[BB * HH];                // layer-0 cell
__device__ float g_c1[BB * HH];                // layer-1 cell
__device__ float g_wpack0[HH * 32 * 128];      // packed w_hh0
__device__ float g_wpack1[HH * 32 * 128];      // packed w_hh1
__device__ float g_wpackI[HH * 32 * 128];      // packed w_ih1

// ---------------- packed f32x2 + fast-math helpers ----------------
__device__ __forceinline__ unsigned long long pk2(float lo, float hi) {
    unsigned long long r;
    asm("mov.b64 %0, {%1, %2};" : "=l"(r) : "f"(lo), "f"(hi));
    return r;
}
__device__ __forceinline__ void fma2(unsigned long long& d, unsigned long long a, unsigned long long b) {
    asm("fma.rn.f32x2 %0, %1, %2, %3;" : "=l"(d) : "l"(a), "l"(b), "l"(d));
}
__device__ __forceinline__ float2 upk2(unsigned long long v) {
    float lo, hi;
    asm("mov.b64 {%0, %1}, %2;" : "=f"(lo), "=f"(hi) : "l"(v));
    return make_float2(lo, hi);
}
__device__ __forceinline__ float tanh_f(float x) {
    float r;
    asm("tanh.approx.f32 %0, %1;" : "=f"(r) : "f"(x));
    return r;
}
__device__ __forceinline__ float sigf(float x) { return fmaf(tanh_f(0.5f * x), 0.5f, 0.5f); }

// 2 row-pairs (packed) x 4 cols micro-tile: 16 MACs in 8 fma2 + 4 packs
__device__ __forceinline__ void mma16(unsigned long long acc[2][4], ulonglong2 av, float4 wv) {
    unsigned long long w0 = pk2(wv.x, wv.x), w1 = pk2(wv.y, wv.y),
                       w2 = pk2(wv.z, wv.z), w3 = pk2(wv.w, wv.w);
    fma2(acc[0][0], av.x, w0); fma2(acc[1][0], av.y, w0);
    fma2(acc[0][1], av.x, w1); fma2(acc[1][1], av.y, w1);
    fma2(acc[0][2], av.x, w2); fma2(acc[1][2], av.y, w2);
    fma2(acc[0][3], av.x, w3); fma2(acc[1][3], av.y, w3);
}

// ---------------- input GEMM (layer 0 only): g_xw(raw) = A(16384 x K) @ W(K x 4096) ----------------
__global__ __launch_bounds__(256) void gemm_xw_kernel(const float* __restrict__ A,
                                                      const float* __restrict__ W, int K) {
    __shared__ __align__(16) float As[2][8][132];
    __shared__ __align__(16) float Bd[2][8][260];
    const int n0 = blockIdx.x * 128, m0 = blockIdx.y * 128;
    const int tid = threadIdx.x;
    const int rg = tid & 15, cg = tid >> 4;
    const int r0 = rg * 8, c0 = cg * 8;
    const int ar = tid >> 1, ak = (tid & 1) * 4;
    const int bk = tid >> 5, bc = (tid & 31) * 4;
    const float* pA = A + (size_t)(m0 + ar) * K + ak;
    const float* pB = W + (size_t)bk * GG + n0 + bc;

    unsigned long long acc[4][8] = {};

    float4 va = *(const float4*)pA;
    float4 vb = *(const float4*)pB;
    As[0][ak + 0][ar] = va.x; As[0][ak + 1][ar] = va.y;
    As[0][ak + 2][ar] = va.z; As[0][ak + 3][ar] = va.w;
    *(float2*)&Bd[0][bk][2 * (bc + 0)] = make_float2(vb.x, vb.x);
    *(float2*)&Bd[0][bk][2 * (bc + 1)] = make_float2(vb.y, vb.y);
    *(float2*)&Bd[0][bk][2 * (bc + 2)] = make_float2(vb.z, vb.z);
    *(float2*)&Bd[0][bk][2 * (bc + 3)] = make_float2(vb.w, vb.w);
    __syncthreads();

    int buf = 0;
    for (int kc = 8; kc <= K; kc += 8) {
        const bool more = (kc < K);
        if (more) {
            va = *(const float4*)(pA + kc);
            vb = *(const float4*)(pB + (size_t)kc * GG);
        }
#pragma unroll
        for (int k = 0; k < 8; k++) {
            ulonglong2 a0 = *(const ulonglong2*)&As[buf][k][r0];
            ulonglong2 a1 = *(const ulonglong2*)&As[buf][k][r0 + 4];
            ulonglong2 w01 = *(const ulonglong2*)&Bd[buf][k][2 * c0];
            ulonglong2 w23 = *(const ulonglong2*)&Bd[buf][k][2 * c0 + 4];
            ulonglong2 w45 = *(const ulonglong2*)&Bd[buf][k][2 * c0 + 8];
            ulonglong2 w67 = *(const ulonglong2*)&Bd[buf][k][2 * c0 + 12];
            unsigned long long avp[4] = {a0.x, a0.y, a1.x, a1.y};
            unsigned long long wr[8] = {w01.x, w01.y, w23.x, w23.y, w45.x, w45.y, w67.x, w67.y};
#pragma unroll
            for (int p = 0; p < 4; p++)
#pragma unroll
                for (int c = 0; c < 8; c++) fma2(acc[p][c], avp[p], wr[c]);
        }
        if (more) {
            int nb = buf ^ 1;
            As[nb][ak + 0][ar] = va.x; As[nb][ak + 1][ar] = va.y;
            As[nb][ak + 2][ar] = va.z; As[nb][ak + 3][ar] = va.w;
            *(float2*)&Bd[nb][bk][2 * (bc + 0)] = make_float2(vb.x, vb.x);
            *(float2*)&Bd[nb][bk][2 * (bc + 1)] = make_float2(vb.y, vb.y);
            *(float2*)&Bd[nb][bk][2 * (bc + 2)] = make_float2(vb.z, vb.z);
            *(float2*)&Bd[nb][bk][2 * (bc + 3)] = make_float2(vb.w, vb.w);
            __syncthreads();
            buf = nb;
        }
    }
#pragma unroll
    for (int p = 0; p < 4; p++) {
        float2 u[8];
#pragma unroll
        for (int c = 0; c < 8; c++) u[c] = upk2(acc[p][c]);
        float* o0 = &g_xw[(size_t)(m0 + r0 + 2 * p) * GG + n0 + c0];
        float* o1 = o0 + GG;
        *(float4*)o0       = make_float4(u[0].x, u[1].x, u[2].x, u[3].x);
        *(float4*)(o0 + 4) = make_float4(u[4].x, u[5].x, u[6].x, u[7].x);
        *(float4*)o1       = make_float4(u[0].y, u[1].y, u[2].y, u[3].y);
        *(float4*)(o1 + 4) = make_float4(u[4].y, u[5].y, u[6].y, u[7].y);
    }
}

// ---------------- pack a (1024 x 4096) weight so block blk owns gate cols {g*H + blk*8 + j} ----------------
__global__ void pack_w_kernel(const float* __restrict__ w, float* __restrict__ dst) {
    const int idx = blockIdx.x * 256 + threadIdx.x;  // < HH*GG
    const int c = idx & 31;
    const int k = (idx >> 5) & (HH - 1);
    const int blk = idx >> 15;
    dst[idx] = w[(size_t)k * GG + (c >> 3) * HH + blk * 8 + (c & 7)];
}

__global__ void init_kernel() {
    const int i = blockIdx.x * 256 + threadIdx.x;
    if (i < BB * HH) {
        g_h0[0][i] = 0.f; g_h0[1][i] = 0.f;
        g_h1[0][i] = 0.f; g_h1[1][i] = 0.f;
        g_c0[i] = 0.f;    g_c1[i] = 0.f;
    }
}

// ---------------- shared step scratch ----------------
struct StepSmem {
    float hsT[2][32][68];  // [k][b] transposed A staging
    float ws[2][32][36];   // [k][c] weight staging
    float Cs[64][36];      // h@w_hh result
    float Xs[64][36];      // input-path tile (loaded xw for L0, computed y0@w_ih1 for L1)
    float redA[8][32], redB[8][32], redC[8][32], redD[8][32];
    float scH[32], shH[32], scX[32], shX[32];
    float c1s[64][9], oss[64][9];
    float scc[8], shc[8];
};

// ---------------- proven 64x32x1024 GEMM core (R14 verbatim) ----------------
__device__ __forceinline__ void gemm_into(const float* __restrict__ A,
                                          const float* __restrict__ wp,
                                          StepSmem& sm, int tid,
                                          unsigned long long acc[2][4]) {
    const int rt = tid & 15, ct = tid >> 4;
    const int r0 = rt * 4, c0 = ct * 4;
    float4 ph[4], pw[2];
#pragma unroll
    for (int i = 0; i < 4; i++) {
        int idx = tid + i * 128;
        ph[i] = *(const float4*)&A[(idx >> 3) * HH + (idx & 7) * 4];
    }
#pragma unroll
    for (int i = 0; i < 2; i++) {
        int idx = tid + i * 128;
        pw[i] = *(const float4*)&wp[(idx >> 3) * 32 + (idx & 7) * 4];
    }
#pragma unroll
    for (int i = 0; i < 4; i++) {
        int idx = tid + i * 128;
        int b = idx >> 3, kq = (idx & 7) * 4;
        sm.hsT[0][kq + 0][b] = ph[i].x; sm.hsT[0][kq + 1][b] = ph[i].y;
        sm.hsT[0][kq + 2][b] = ph[i].z; sm.hsT[0][kq + 3][b] = ph[i].w;
    }
#pragma unroll
    for (int i = 0; i < 2; i++) {
        int idx = tid + i * 128;
        *(float4*)&sm.ws[0][idx >> 3][(idx & 7) * 4] = pw[i];
    }
    __syncthreads();

    int buf = 0;
    for (int kc = 32; kc <= HH; kc += 32) {
        const bool more = (kc < HH);
        if (more) {
#pragma unroll
            for (int i = 0; i < 4; i++) {
                int idx = tid + i * 128;
                ph[i] = *(const float4*)&A[(idx >> 3) * HH + kc + (idx & 7) * 4];
            }
#pragma unroll
            for (int i = 0; i < 2; i++) {
                int idx = tid + i * 128;
                pw[i] = *(const float4*)&wp[(kc + (idx >> 3)) * 32 + (idx & 7) * 4];
            }
        }
#pragma unroll
        for (int k = 0; k < 32; k++) {
            ulonglong2 av = *(const ulonglong2*)&sm.hsT[buf][k][r0];
            float4 wv = *(const float4*)&sm.ws[buf][k][c0];
            mma16(acc, av, wv);
        }
        if (more) {
            int nb = buf ^ 1;
#pragma unroll
            for (int i = 0; i < 4; i++) {
                int idx = tid + i * 128;
                int b = idx >> 3, kq = (idx & 7) * 4;
                sm.hsT[nb][kq + 0][b] = ph[i].x; sm.hsT[nb][kq + 1][b] = ph[i].y;
                sm.hsT[nb][kq + 2][b] = ph[i].z; sm.hsT[nb][kq + 3][b] = ph[i].w;
            }
#pragma unroll
            for (int i = 0; i < 2; i++) {
                int idx = tid + i * 128;
                *(float4*)&sm.ws[nb][idx >> 3][(idx & 7) * 4] = pw[i];
            }
            __syncthreads();
            buf = nb;
        }
    }
    __syncthreads();
}

__device__ __forceinline__ void store_acc(float dst[64][36], unsigned long long acc[2][4],
                                          int r0, int c0) {
#pragma unroll
    for (int rp = 0; rp < 2; rp++) {
        float2 u0 = upk2(acc[rp][0]), u1 = upk2(acc[rp][1]),
               u2 = upk2(acc[rp][2]), u3 = upk2(acc[rp][3]);
        *(float4*)&dst[r0 + 2 * rp][c0]     = make_float4(u0.x, u1.x, u2.x, u3.x);
        *(float4*)&dst[r0 + 2 * rp + 1][c0] = make_float4(u0.y, u1.y, u2.y, u3.y);
    }
}

// ---------------- full BN-LSTM step for one block's 8 h-cols / 32 gate-cols ----------------
// ROLE 0: Xs loaded from precomputed g_xw. ROLE 1: Xs computed as y0[t] @ wp_ih.
template <int ROLE>
__device__ __forceinline__ void step_body(
    int t, int blk, StepSmem& sm,
    const float* __restrict__ hin, float* __restrict__ hout, float* __restrict__ cst,
    const float* __restrict__ wp_hh, const float* __restrict__ wp_ih,
    const float* __restrict__ ghh, const float* __restrict__ bthh,
    const float* __restrict__ gih, const float* __restrict__ btih,
    const float* __restrict__ bias,
    const float* __restrict__ gcb, const float* __restrict__ btcb,
    const int* __restrict__ length,
    float* __restrict__ y_out, float* __restrict__ hn_out, float* __restrict__ cn_out) {
    const int tid = threadIdx.x;

    // ---- early prefetch: cell state + lengths (+ xw slice for ROLE 0) ----
    float4 xwv[4]; float coldr[4]; int lenr[4];
#pragma unroll
    for (int i = 0; i < 4; i++) {
        int f = tid + i * 128;
        int b = f >> 3, sub = f & 7;
        coldr[i] = cst[b * HH + blk * 8 + sub];
        lenr[i] = length[b];
        if (ROLE == 0) {
            int gate = sub >> 1, jj = (sub & 1) * 4;
            xwv[i] = __ldg((const float4*)&g_xw[((size_t)t * BB + b) * GG + gate * HH + blk * 8 + jj]);
        }
    }

    const int rt = tid & 15, ct = tid >> 4;
    const int r0 = rt * 4, c0 = ct * 4;
    unsigned long long acc[2][4];

    // ---- ROLE 1: compute Xs = y0[t] @ wp_ih (same proven core) ----
    if (ROLE == 1) {
#pragma unroll
        for (int r = 0; r < 2; r++)
#pragma unroll
            for (int c = 0; c < 4; c++) acc[r][c] = 0ull;
        gemm_into(g_y0 + (size_t)t * BB * HH, wp_ih, sm, tid, acc);
        store_acc(sm.Xs, acc, r0, c0);
    }

    // ---- recurrent GEMM: Cs = hin @ wp_hh ----
#pragma unroll
    for (int r = 0; r < 2; r++)
#pragma unroll
        for (int c = 0; c < 4; c++) acc[r][c] = 0ull;
    gemm_into(hin, wp_hh, sm, tid, acc);
    store_acc(sm.Cs, acc, r0, c0);

    if (ROLE == 0) {
#pragma unroll
        for (int i = 0; i < 4; i++) {
            int f = tid + i * 128;
            int b = f >> 3, sub = f & 7;
            int gate = sub >> 1, jj = (sub & 1) * 4;
            *(float4*)&sm.Xs[b][gate * 8 + jj] = xwv[i];
        }
    }
    __syncthreads();

    // ---- BN stats over batch for hh-GEMM and ih columns ----
    {
        int c = tid & 31, q = tid >> 5;
        float sC = 0.f, s2C = 0.f, sX = 0.f, s2X = 0.f;
#pragma unroll
        for (int b = q * 16; b < q * 16 + 16; b++) {
            float v = sm.Cs[b][c]; sC += v; s2C += v * v;
            float u = sm.Xs[b][c]; sX += u; s2X += u * u;
        }
        sm.redA[q][c] = sC; sm.redB[q][c] = s2C;
        sm.redC[q][c] = sX; sm.redD[q][c] = s2X;
    }
    __syncthreads();
    if (tid < 32) {
        float sC = sm.redA[0][tid] + sm.redA[1][tid] + sm.redA[2][tid] + sm.redA[3][tid];
        float s2C = sm.redB[0][tid] + sm.redB[1][tid] + sm.redB[2][tid] + sm.redB[3][tid];
        float sX = sm.redC[0][tid] + sm.redC[1][tid] + sm.redC[2][tid] + sm.redC[3][tid];
        float s2X = sm.redD[0][tid] + sm.redD[1][tid] + sm.redD[2][tid] + sm.redD[3][tid];
        int col = (tid >> 3) * HH + blk * 8 + (tid & 7);
        float muC = sC * (1.f / 64.f);
        float varC = fmaxf(s2C * (1.f / 64.f) - muC * muC, 0.f);
        float a = ghh[col] * rsqrtf(varC + EPSB);
        sm.scH[tid] = a; sm.shH[tid] = bthh[col] - muC * a;
        float muX = sX * (1.f / 64.f);
        float varX = fmaxf(s2X * (1.f / 64.f) - muX * muX, 0.f);
        float e = gih[col] * rsqrtf(varX + EPSB);
        sm.scX[tid] = e; sm.shX[tid] = btih[col] + bias[col] - muX * e;
    }
    __syncthreads();

    // ---- gates + cell update ----
#pragma unroll
    for (int i = 0; i < 4; i++) {
        int f = tid + i * 128;
        int b = f >> 3, j = f & 7;
        float pre[4];
#pragma unroll
        for (int g = 0; g < 4; g++) {
            int c = g * 8 + j;
            pre[g] = sm.Cs[b][c] * sm.scH[c] + sm.shH[c] + sm.Xs[b][c] * sm.scX[c] + sm.shX[c];
        }
        float c1 = sigf(pre[0]) * coldr[i] + sigf(pre[1]) * tanh_f(pre[3]);
        sm.c1s[b][j] = c1;
        sm.oss[b][j] = sigf(pre[2]);
    }
    __syncthreads();

    // ---- BN stats over batch for the 8 cell columns ----
    if (tid < 64) {
        int j = tid & 7, q = tid >> 3;
        float s = 0.f, s2 = 0.f;
#pragma unroll
        for (int b = q * 8; b < q * 8 + 8; b++) {
            float v = sm.c1s[b][j]; s += v; s2 += v * v;
        }
        sm.redA[q][j] = s; sm.redB[q][j] = s2;
    }
    __syncthreads();
    if (tid < 8) {
        float s = 0.f, s2 = 0.f;
#pragma unroll
        for (int q = 0; q < 8; q++) { s += sm.redA[q][tid]; s2 += sm.redB[q][tid]; }
        float mu = s * (1.f / 64.f);
        float var = fmaxf(s2 * (1.f / 64.f) - mu * mu, 0.f);
        int hcol = blk * 8 + tid;
        float a = gcb[hcol] * rsqrtf(var + EPSB);
        sm.scc[tid] = a; sm.shc[tid] = btcb[hcol] - mu * a;
    }
    __syncthreads();

    // ---- h update with length mask; write h, c, y (+ finals at t = TT-1) ----
#pragma unroll
    for (int i = 0; i < 4; i++) {
        int f = tid + i * 128;
        int b = f >> 3, j = f & 7;
        int hcol = blk * 8 + j;
        float c1 = sm.c1s[b][j];
        float h1 = sm.oss[b][j] * tanh_f(c1 * sm.scc[j] + sm.shc[j]);
        bool m = t < lenr[i];
        float hold = hin[b * HH + hcol];
        float hn = m ? h1 : hold;
        float cn = m ? c1 : coldr[i];
        hout[b * HH + hcol] = hn;
        cst[b * HH + hcol] = cn;
        y_out[((size_t)t * BB + b) * HH + hcol] = hn;
        if (t == TT - 1) {
            hn_out[b * HH + hcol] = hn;
            cn_out[b * HH + hcol] = cn;
        }
    }
}

// ---------------- tick kernel: layer-0 step s + layer-1 step s-1, same launch ----------------
// Grid 296: blocks [0,148) -> L0 (blk = bid, active blk<128, s<TT);
//           blocks [148,296) -> L1 (blk = bid-148, active blk<128, s>=1).
// The +148 offset pairs one L0 block with one L1 block per SM (LUT_classic[bid%148]).
__global__ __launch_bounds__(128) void lstm_tick_kernel(
    int s,
    const float* __restrict__ ghh0, const float* __restrict__ bthh0,
    const float* __restrict__ gih0, const float* __restrict__ btih0,
    const float* __restrict__ b0,
    const float* __restrict__ gc0, const float* __restrict__ btc0,
    const float* __restrict__ ghh1, const float* __restrict__ bthh1,
    const float* __restrict__ gih1, const float* __restrict__ btih1,
    const float* __restrict__ b1,
    const float* __restrict__ gc1, const float* __restrict__ btc1,
    const int* __restrict__ length,
    float* __restrict__ y1, float* __restrict__ hn_out, float* __restrict__ cn_out) {
    __shared__ StepSmem sm;
    const int bid = blockIdx.x;
    if (bid < 148) {
        const int blk = bid;
        if (blk >= 128 || s >= TT) return;
        step_body<0>(s, blk, sm,
                     g_h0[s & 1], g_h0[(s & 1) ^ 1], g_c0,
                     g_wpack0 + (size_t)blk * 32768, nullptr,
                     ghh0, bthh0, gih0, btih0, b0, gc0, btc0, length,
                     g_y0, hn_out, cn_out);
    } else {
        const int blk = bid - 148;
        if (blk >= 128 || s < 1) return;
        const int t = s - 1;
        step_body<1>(t, blk, sm,
                     g_h1[t & 1], g_h1[(t & 1) ^ 1], g_c1,
                     g_wpack1 + (size_t)blk * 32768, g_wpackI + (size_t)blk * 32768,
                     ghh1, bthh1, gih1, btih1, b1, gc1, btc1, length,
                     y1, hn_out + BB * HH, cn_out + BB * HH);
    }
}

// ---------------- host orchestration ----------------
extern "C" void kernel_launch(void* const* d_in, const int* in_sizes, int n_in,
                              void* d_out, int out_size) {
    const float* x     = (const float*)d_in[0];
    const int* length  = (const int*)d_in[1];
    const float* w_ih0 = (const float*)d_in[2];
    const float* w_hh0 = (const float*)d_in[3];
    const float* b0    = (const float*)d_in[4];
    const float* gih0  = (const float*)d_in[5];
    const float* btih0 = (const float*)d_in[6];
    const float* ghh0  = (const float*)d_in[7];
    const float* bthh0 = (const float*)d_in[8];
    const float* gc0   = (const float*)d_in[9];
    const float* btc0  = (const float*)d_in[10];
    const float* w_ih1 = (const float*)d_in[11];
    const float* w_hh1 = (const float*)d_in[12];
    const float* b1    = (const float*)d_in[13];
    const float* gih1  = (const float*)d_in[14];
    const float* btih1 = (const float*)d_in[15];
    const float* ghh1  = (const float*)d_in[16];
    const float* bthh1 = (const float*)d_in[17];
    const float* gc1   = (const float*)d_in[18];
    const float* btc1  = (const float*)d_in[19];

    float* out = (float*)d_out;
    float* y1 = out;
    float* hn = out + (size_t)TT * BB * HH;
    float* cn = hn + 2 * BB * HH;

    float *p_w0 = nullptr, *p_w1 = nullptr, *p_wI = nullptr;
    cudaGetSymbolAddress((void**)&p_w0, g_wpack0);
    cudaGetSymbolAddress((void**)&p_w1, g_wpack1);
    cudaGetSymbolAddress((void**)&p_wI, g_wpackI);

    const dim3 ggrid(GG / 128, (TT * BB) / 128);
    const int packgrid = (HH * GG) / 256;
    const int initgrid = (BB * HH) / 256;

    // precompute: layer-0 input GEMM + weight packs + state init
    gemm_xw_kernel<<<ggrid, 256>>>(x, w_ih0, DD);
    pack_w_kernel<<<packgrid, 256>>>(w_hh0, p_w0);
    pack_w_kernel<<<packgrid, 256>>>(w_hh1, p_w1);
    pack_w_kernel<<<packgrid, 256>>>(w_ih1, p_wI);
    init_kernel<<<initgrid, 256>>>();

    // pipelined recurrence: L0 step s and L1 step s-1 share each launch
    for (int s = 0; s <= TT; s++)
        lstm_tick_kernel<<<296, 128>>>(s,
                                       ghh0, bthh0, gih0, btih0, b0, gc0, btc0,
                                       ghh1, bthh1, gih1, btih1, b1, gc1, btc1,
                                       length, y1, hn, cn);
}

// round 16
// speedup vs baseline: 1.5687x; 1.0471x over previous
#include <cuda_runtime.h>
#include <cstdint>
#include <cstddef>

#define TT 256
#define BB 64
#define DD 512
#define HH 1024
#define GG 4096
#define EPSB 1e-5f

// ---------------- scratch (device globals: no allocation allowed) ----------------
__device__ float g_xw[(size_t)TT * BB * GG];   // 256 MB: raw x@w_ih0 (layer-0 input GEMM)
__device__ float g_xw1[(size_t)TT * BB * GG];  // 256 MB: raw y0@w_ih1 (role-B output)
__device__ float g_y0[(size_t)TT * BB * HH];   // 64 MB: layer-0 output (= layer-1 input)
__device__ float g_h0[2][BB * HH];             // layer-0 h ping-pong
__device__ float g_h1[2][BB * HH];             // layer-1 h ping-pong
__device__ float g_c0[BB * HH];                // layer-0 cell
__device__ float g_c1[BB * HH];                // layer-1 cell
__device__ float g_wpack0[HH * 32 * 128];      // packed w_hh0
__device__ float g_wpack1[HH * 32 * 128];      // packed w_hh1
__device__ float g_wpackI[HH * 32 * 128];      // packed w_ih1

// ---------------- packed f32x2 + fast-math helpers ----------------
__device__ __forceinline__ unsigned long long pk2(float lo, float hi) {
    unsigned long long r;
    asm("mov.b64 %0, {%1, %2};" : "=l"(r) : "f"(lo), "f"(hi));
    return r;
}
__device__ __forceinline__ void fma2(unsigned long long& d, unsigned long long a, unsigned long long b) {
    asm("fma.rn.f32x2 %0, %1, %2, %3;" : "=l"(d) : "l"(a), "l"(b), "l"(d));
}
__device__ __forceinline__ float2 upk2(unsigned long long v) {
    float lo, hi;
    asm("mov.b64 {%0, %1}, %2;" : "=f"(lo), "=f"(hi) : "l"(v));
    return make_float2(lo, hi);
}
__device__ __forceinline__ float tanh_f(float x) {
    float r;
    asm("tanh.approx.f32 %0, %1;" : "=f"(r) : "f"(x));
    return r;
}
__device__ __forceinline__ float sigf(float x) { return fmaf(tanh_f(0.5f * x), 0.5f, 0.5f); }

// 2 row-pairs (packed) x 4 cols micro-tile: 16 MACs in 8 fma2 + 4 packs
__device__ __forceinline__ void mma16(unsigned long long acc[2][4], ulonglong2 av, float4 wv) {
    unsigned long long w0 = pk2(wv.x, wv.x), w1 = pk2(wv.y, wv.y),
                       w2 = pk2(wv.z, wv.z), w3 = pk2(wv.w, wv.w);
    fma2(acc[0][0], av.x, w0); fma2(acc[1][0], av.y, w0);
    fma2(acc[0][1], av.x, w1); fma2(acc[1][1], av.y, w1);
    fma2(acc[0][2], av.x, w2); fma2(acc[1][2], av.y, w2);
    fma2(acc[0][3], av.x, w3); fma2(acc[1][3], av.y, w3);
}

// ---------------- input GEMM (layer 0 only): g_xw(raw) = A(16384 x K) @ W(K x 4096) ----------------
__global__ __launch_bounds__(256) void gemm_xw_kernel(const float* __restrict__ A,
                                                      const float* __restrict__ W, int K) {
    __shared__ __align__(16) float As[2][8][132];
    __shared__ __align__(16) float Bd[2][8][260];
    const int n0 = blockIdx.x * 128, m0 = blockIdx.y * 128;
    const int tid = threadIdx.x;
    const int rg = tid & 15, cg = tid >> 4;
    const int r0 = rg * 8, c0 = cg * 8;
    const int ar = tid >> 1, ak = (tid & 1) * 4;
    const int bk = tid >> 5, bc = (tid & 31) * 4;
    const float* pA = A + (size_t)(m0 + ar) * K + ak;
    const float* pB = W + (size_t)bk * GG + n0 + bc;

    unsigned long long acc[4][8] = {};

    float4 va = *(const float4*)pA;
    float4 vb = *(const float4*)pB;
    As[0][ak + 0][ar] = va.x; As[0][ak + 1][ar] = va.y;
    As[0][ak + 2][ar] = va.z; As[0][ak + 3][ar] = va.w;
    *(float2*)&Bd[0][bk][2 * (bc + 0)] = make_float2(vb.x, vb.x);
    *(float2*)&Bd[0][bk][2 * (bc + 1)] = make_float2(vb.y, vb.y);
    *(float2*)&Bd[0][bk][2 * (bc + 2)] = make_float2(vb.z, vb.z);
    *(float2*)&Bd[0][bk][2 * (bc + 3)] = make_float2(vb.w, vb.w);
    __syncthreads();

    int buf = 0;
    for (int kc = 8; kc <= K; kc += 8) {
        const bool more = (kc < K);
        if (more) {
            va = *(const float4*)(pA + kc);
            vb = *(const float4*)(pB + (size_t)kc * GG);
        }
#pragma unroll
        for (int k = 0; k < 8; k++) {
            ulonglong2 a0 = *(const ulonglong2*)&As[buf][k][r0];
            ulonglong2 a1 = *(const ulonglong2*)&As[buf][k][r0 + 4];
            ulonglong2 w01 = *(const ulonglong2*)&Bd[buf][k][2 * c0];
            ulonglong2 w23 = *(const ulonglong2*)&Bd[buf][k][2 * c0 + 4];
            ulonglong2 w45 = *(const ulonglong2*)&Bd[buf][k][2 * c0 + 8];
            ulonglong2 w67 = *(const ulonglong2*)&Bd[buf][k][2 * c0 + 12];
            unsigned long long avp[4] = {a0.x, a0.y, a1.x, a1.y};
            unsigned long long wr[8] = {w01.x, w01.y, w23.x, w23.y, w45.x, w45.y, w67.x, w67.y};
#pragma unroll
            for (int p = 0; p < 4; p++)
#pragma unroll
                for (int c = 0; c < 8; c++) fma2(acc[p][c], avp[p], wr[c]);
        }
        if (more) {
            int nb = buf ^ 1;
            As[nb][ak + 0][ar] = va.x; As[nb][ak + 1][ar] = va.y;
            As[nb][ak + 2][ar] = va.z; As[nb][ak + 3][ar] = va.w;
            *(float2*)&Bd[nb][bk][2 * (bc + 0)] = make_float2(vb.x, vb.x);
            *(float2*)&Bd[nb][bk][2 * (bc + 1)] = make_float2(vb.y, vb.y);
            *(float2*)&Bd[nb][bk][2 * (bc + 2)] = make_float2(vb.z, vb.z);
            *(float2*)&Bd[nb][bk][2 * (bc + 3)] = make_float2(vb.w, vb.w);
            __syncthreads();
            buf = nb;
        }
    }
#pragma unroll
    for (int p = 0; p < 4; p++) {
        float2 u[8];
#pragma unroll
        for (int c = 0; c < 8; c++) u[c] = upk2(acc[p][c]);
        float* o0 = &g_xw[(size_t)(m0 + r0 + 2 * p) * GG + n0 + c0];
        float* o1 = o0 + GG;
        *(float4*)o0       = make_float4(u[0].x, u[1].x, u[2].x, u[3].x);
        *(float4*)(o0 + 4) = make_float4(u[4].x, u[5].x, u[6].x, u[7].x);
        *(float4*)o1       = make_float4(u[0].y, u[1].y, u[2].y, u[3].y);
        *(float4*)(o1 + 4) = make_float4(u[4].y, u[5].y, u[6].y, u[7].y);
    }
}

// ---------------- pack a (1024 x 4096) weight so block blk owns gate cols {g*H + blk*8 + j} ----------------
__global__ void pack_w_kernel(const float* __restrict__ w, float* __restrict__ dst) {
    const int idx = blockIdx.x * 256 + threadIdx.x;  // < HH*GG
    const int c = idx & 31;
    const int k = (idx >> 5) & (HH - 1);
    const int blk = idx >> 15;
    dst[idx] = w[(size_t)k * GG + (c >> 3) * HH + blk * 8 + (c & 7)];
}

__global__ void init_kernel() {
    const int i = blockIdx.x * 256 + threadIdx.x;
    if (i < BB * HH) {
        g_h0[0][i] = 0.f; g_h0[1][i] = 0.f;
        g_h1[0][i] = 0.f; g_h1[1][i] = 0.f;
        g_c0[i] = 0.f;    g_c1[i] = 0.f;
    }
}

// ---------------- shared step scratch ----------------
struct StepSmem {
    float hsT[2][32][68];  // [k][b] transposed A staging
    float ws[2][32][36];   // [k][c] weight staging
    float Cs[64][36];      // h@w_hh result
    float Xs[64][36];      // input-path tile
    float redA[8][32], redB[8][32], redC[8][32], redD[8][32];
    float scH[32], shH[32], scX[32], shX[32];
    float c1s[64][9], oss[64][9];
    float scc[8], shc[8];
};

// ---------------- proven 64x32x1024 GEMM core ----------------
__device__ __forceinline__ void gemm_into(const float* __restrict__ A,
                                          const float* __restrict__ wp,
                                          StepSmem& sm, int tid,
                                          unsigned long long acc[2][4]) {
    const int rt = tid & 15, ct = tid >> 4;
    const int r0 = rt * 4, c0 = ct * 4;
    float4 ph[4], pw[2];
#pragma unroll
    for (int i = 0; i < 4; i++) {
        int idx = tid + i * 128;
        ph[i] = *(const float4*)&A[(idx >> 3) * HH + (idx & 7) * 4];
    }
#pragma unroll
    for (int i = 0; i < 2; i++) {
        int idx = tid + i * 128;
        pw[i] = *(const float4*)&wp[(idx >> 3) * 32 + (idx & 7) * 4];
    }
#pragma unroll
    for (int i = 0; i < 4; i++) {
        int idx = tid + i * 128;
        int b = idx >> 3, kq = (idx & 7) * 4;
        sm.hsT[0][kq + 0][b] = ph[i].x; sm.hsT[0][kq + 1][b] = ph[i].y;
        sm.hsT[0][kq + 2][b] = ph[i].z; sm.hsT[0][kq + 3][b] = ph[i].w;
    }
#pragma unroll
    for (int i = 0; i < 2; i++) {
        int idx = tid + i * 128;
        *(float4*)&sm.ws[0][idx >> 3][(idx & 7) * 4] = pw[i];
    }
    __syncthreads();

    int buf = 0;
    for (int kc = 32; kc <= HH; kc += 32) {
        const bool more = (kc < HH);
        if (more) {
#pragma unroll
            for (int i = 0; i < 4; i++) {
                int idx = tid + i * 128;
                ph[i] = *(const float4*)&A[(idx >> 3) * HH + kc + (idx & 7) * 4];
            }
#pragma unroll
            for (int i = 0; i < 2; i++) {
                int idx = tid + i * 128;
                pw[i] = *(const float4*)&wp[(kc + (idx >> 3)) * 32 + (idx & 7) * 4];
            }
        }
#pragma unroll
        for (int k = 0; k < 32; k++) {
            ulonglong2 av = *(const ulonglong2*)&sm.hsT[buf][k][r0];
            float4 wv = *(const float4*)&sm.ws[buf][k][c0];
            mma16(acc, av, wv);
        }
        if (more) {
            int nb = buf ^ 1;
#pragma unroll
            for (int i = 0; i < 4; i++) {
                int idx = tid + i * 128;
                int b = idx >> 3, kq = (idx & 7) * 4;
                sm.hsT[nb][kq + 0][b] = ph[i].x; sm.hsT[nb][kq + 1][b] = ph[i].y;
                sm.hsT[nb][kq + 2][b] = ph[i].z; sm.hsT[nb][kq + 3][b] = ph[i].w;
            }
#pragma unroll
            for (int i = 0; i < 2; i++) {
                int idx = tid + i * 128;
                *(float4*)&sm.ws[nb][idx >> 3][(idx & 7) * 4] = pw[i];
            }
            __syncthreads();
            buf = nb;
        }
    }
    __syncthreads();
}

__device__ __forceinline__ void store_acc(float dst[64][36], unsigned long long acc[2][4],
                                          int r0, int c0) {
#pragma unroll
    for (int rp = 0; rp < 2; rp++) {
        float2 u0 = upk2(acc[rp][0]), u1 = upk2(acc[rp][1]),
               u2 = upk2(acc[rp][2]), u3 = upk2(acc[rp][3]);
        *(float4*)&dst[r0 + 2 * rp][c0]     = make_float4(u0.x, u1.x, u2.x, u3.x);
        *(float4*)&dst[r0 + 2 * rp + 1][c0] = make_float4(u0.y, u1.y, u2.y, u3.y);
    }
}

// ---------------- full BN-LSTM step for one block's 8 h-cols / 32 gate-cols ----------------
// Xs is loaded from a precomputed raw input-GEMM buffer (xw_base).
__device__ __forceinline__ void step_body(
    int t, int blk, StepSmem& sm, const float* __restrict__ xw_base,
    const float* __restrict__ hin, float* __restrict__ hout, float* __restrict__ cst,
    const float* __restrict__ wp_hh,
    const float* __restrict__ ghh, const float* __restrict__ bthh,
    const float* __restrict__ gih, const float* __restrict__ btih,
    const float* __restrict__ bias,
    const float* __restrict__ gcb, const float* __restrict__ btcb,
    const int* __restrict__ length,
    float* __restrict__ y_out, float* __restrict__ hn_out, float* __restrict__ cn_out) {
    const int tid = threadIdx.x;

    // ---- early prefetch: xw slice + cell state + lengths ----
    float4 xwv[4]; float coldr[4]; int lenr[4];
#pragma unroll
    for (int i = 0; i < 4; i++) {
        int f = tid + i * 128;
        int b = f >> 3, sub = f & 7;
        int gate = sub >> 1, jj = (sub & 1) * 4;
        xwv[i] = __ldg((const float4*)&xw_base[((size_t)t * BB + b) * GG + gate * HH + blk * 8 + jj]);
        coldr[i] = cst[b * HH + blk * 8 + sub];
        lenr[i] = length[b];
    }

    const int rt = tid & 15, ct = tid >> 4;
    const int r0 = rt * 4, c0 = ct * 4;
    unsigned long long acc[2][4];
#pragma unroll
    for (int r = 0; r < 2; r++)
#pragma unroll
        for (int c = 0; c < 4; c++) acc[r][c] = 0ull;
    gemm_into(hin, wp_hh, sm, tid, acc);
    store_acc(sm.Cs, acc, r0, c0);

#pragma unroll
    for (int i = 0; i < 4; i++) {
        int f = tid + i * 128;
        int b = f >> 3, sub = f & 7;
        int gate = sub >> 1, jj = (sub & 1) * 4;
        *(float4*)&sm.Xs[b][gate * 8 + jj] = xwv[i];
    }
    __syncthreads();

    // ---- BN stats over batch for hh-GEMM and ih columns ----
    {
        int c = tid & 31, q = tid >> 5;
        float sC = 0.f, s2C = 0.f, sX = 0.f, s2X = 0.f;
#pragma unroll
        for (int b = q * 16; b < q * 16 + 16; b++) {
            float v = sm.Cs[b][c]; sC += v; s2C += v * v;
            float u = sm.Xs[b][c]; sX += u; s2X += u * u;
        }
        sm.redA[q][c] = sC; sm.redB[q][c] = s2C;
        sm.redC[q][c] = sX; sm.redD[q][c] = s2X;
    }
    __syncthreads();
    if (tid < 32) {
        float sC = sm.redA[0][tid] + sm.redA[1][tid] + sm.redA[2][tid] + sm.redA[3][tid];
        float s2C = sm.redB[0][tid] + sm.redB[1][tid] + sm.redB[2][tid] + sm.redB[3][tid];
        float sX = sm.redC[0][tid] + sm.redC[1][tid] + sm.redC[2][tid] + sm.redC[3][tid];
        float s2X = sm.redD[0][tid] + sm.redD[1][tid] + sm.redD[2][tid] + sm.redD[3][tid];
        int col = (tid >> 3) * HH + blk * 8 + (tid & 7);
        float muC = sC * (1.f / 64.f);
        float varC = fmaxf(s2C * (1.f / 64.f) - muC * muC, 0.f);
        float a = ghh[col] * rsqrtf(varC + EPSB);
        sm.scH[tid] = a; sm.shH[tid] = bthh[col] - muC * a;
        float muX = sX * (1.f / 64.f);
        float varX = fmaxf(s2X * (1.f / 64.f) - muX * muX, 0.f);
        float e = gih[col] * rsqrtf(varX + EPSB);
        sm.scX[tid] = e; sm.shX[tid] = btih[col] + bias[col] - muX * e;
    }
    __syncthreads();

    // ---- gates + cell update ----
#pragma unroll
    for (int i = 0; i < 4; i++) {
        int f = tid + i * 128;
        int b = f >> 3, j = f & 7;
        float pre[4];
#pragma unroll
        for (int g = 0; g < 4; g++) {
            int c = g * 8 + j;
            pre[g] = sm.Cs[b][c] * sm.scH[c] + sm.shH[c] + sm.Xs[b][c] * sm.scX[c] + sm.shX[c];
        }
        float c1 = sigf(pre[0]) * coldr[i] + sigf(pre[1]) * tanh_f(pre[3]);
        sm.c1s[b][j] = c1;
        sm.oss[b][j] = sigf(pre[2]);
    }
    __syncthreads();

    // ---- BN stats over batch for the 8 cell columns ----
    if (tid < 64) {
        int j = tid & 7, q = tid >> 3;
        float s = 0.f, s2 = 0.f;
#pragma unroll
        for (int b = q * 8; b < q * 8 + 8; b++) {
            float v = sm.c1s[b][j]; s += v; s2 += v * v;
        }
        sm.redA[q][j] = s; sm.redB[q][j] = s2;
    }
    __syncthreads();
    if (tid < 8) {
        float s = 0.f, s2 = 0.f;
#pragma unroll
        for (int q = 0; q < 8; q++) { s += sm.redA[q][tid]; s2 += sm.redB[q][tid]; }
        float mu = s * (1.f / 64.f);
        float var = fmaxf(s2 * (1.f / 64.f) - mu * mu, 0.f);
        int hcol = blk * 8 + tid;
        float a = gcb[hcol] * rsqrtf(var + EPSB);
        sm.scc[tid] = a; sm.shc[tid] = btcb[hcol] - mu * a;
    }
    __syncthreads();

    // ---- h update with length mask; write h, c, y (+ finals at t = TT-1) ----
#pragma unroll
    for (int i = 0; i < 4; i++) {
        int f = tid + i * 128;
        int b = f >> 3, j = f & 7;
        int hcol = blk * 8 + j;
        float c1 = sm.c1s[b][j];
        float h1 = sm.oss[b][j] * tanh_f(c1 * sm.scc[j] + sm.shc[j]);
        bool m = t < lenr[i];
        float hold = hin[b * HH + hcol];
        float hn = m ? h1 : hold;
        float cn = m ? c1 : coldr[i];
        hout[b * HH + hcol] = hn;
        cst[b * HH + hcol] = cn;
        y_out[((size_t)t * BB + b) * HH + hcol] = hn;
        if (t == TT - 1) {
            hn_out[b * HH + hcol] = hn;
            cn_out[b * HH + hcol] = cn;
        }
    }
}

// ---------------- role B: g_xw1[t] tile = y0[t](64x1024) @ wpI(1024x32), raw ----------------
__device__ __forceinline__ void gemmB_body(int t, int blk, StepSmem& sm,
                                           const float* __restrict__ wpI) {
    const int tid = threadIdx.x;
    const int rt = tid & 15, ct = tid >> 4;
    const int r0 = rt * 4, c0 = ct * 4;
    unsigned long long acc[2][4];
#pragma unroll
    for (int r = 0; r < 2; r++)
#pragma unroll
        for (int c = 0; c < 4; c++) acc[r][c] = 0ull;
    gemm_into(g_y0 + (size_t)t * BB * HH, wpI, sm, tid, acc);

    // write tile to g_xw1 in the exact layout step_body's ROLE-0 load expects:
    // local col c -> global col (c>>3)*HH + blk*8 + (c&7); c0 is a multiple of 4,
    // so the quad [c0, c0+4) stays within one gate and is contiguous in memory.
    const int gate = c0 >> 3, jj = c0 & 7;
    float* base = g_xw1 + (size_t)t * BB * GG + gate * HH + blk * 8 + jj;
#pragma unroll
    for (int rp = 0; rp < 2; rp++) {
        float2 u0 = upk2(acc[rp][0]), u1 = upk2(acc[rp][1]),
               u2 = upk2(acc[rp][2]), u3 = upk2(acc[rp][3]);
        *(float4*)&base[(size_t)(r0 + 2 * rp) * GG]     = make_float4(u0.x, u1.x, u2.x, u3.x);
        *(float4*)&base[(size_t)(r0 + 2 * rp + 1) * GG] = make_float4(u0.y, u1.y, u2.y, u3.y);
    }
}

// ---------------- tick kernel: 3 balanced roles, one of each per SM ----------------
// Grid 444 = 3*148. role = bid/148, blk = bid%148 (active blk<128).
//   role 0: layer-0 step s            (s < TT)
//   role 1: input GEMM for t = s-1    (1 <= s <= TT)
//   role 2: layer-1 step t = s-2      (s >= 2)
// All cross-role dependencies are satisfied by previous launches.
__global__ __launch_bounds__(128) void lstm_tick_kernel(
    int s,
    const float* __restrict__ ghh0, const float* __restrict__ bthh0,
    const float* __restrict__ gih0, const float* __restrict__ btih0,
    const float* __restrict__ b0,
    const float* __restrict__ gc0, const float* __restrict__ btc0,
    const float* __restrict__ ghh1, const float* __restrict__ bthh1,
    const float* __restrict__ gih1, const float* __restrict__ btih1,
    const float* __restrict__ b1,
    const float* __restrict__ gc1, const float* __restrict__ btc1,
    const int* __restrict__ length,
    float* __restrict__ y1, float* __restrict__ hn_out, float* __restrict__ cn_out) {
    __shared__ StepSmem sm;
    const int bid = blockIdx.x;
    const int role = bid < 148 ? 0 : (bid < 296 ? 1 : 2);
    const int blk = bid - role * 148;
    if (blk >= 128) return;

    if (role == 0) {
        if (s >= TT) return;
        step_body(s, blk, sm, g_xw,
                  g_h0[s & 1], g_h0[(s & 1) ^ 1], g_c0,
                  g_wpack0 + (size_t)blk * 32768,
                  ghh0, bthh0, gih0, btih0, b0, gc0, btc0, length,
                  g_y0, hn_out, cn_out);
    } else if (role == 1) {
        if (s < 1 || s > TT) return;
        gemmB_body(s - 1, blk, sm, g_wpackI + (size_t)blk * 32768);
    } else {
        if (s < 2) return;
        const int t = s - 2;
        step_body(t, blk, sm, g_xw1,
                  g_h1[t & 1], g_h1[(t & 1) ^ 1], g_c1,
                  g_wpack1 + (size_t)blk * 32768,
                  ghh1, bthh1, gih1, btih1, b1, gc1, btc1, length,
                  y1, hn_out + BB * HH, cn_out + BB * HH);
    }
}

// ---------------- host orchestration ----------------
extern "C" void kernel_launch(void* const* d_in, const int* in_sizes, int n_in,
                              void* d_out, int out_size) {
    const float* x     = (const float*)d_in[0];
    const int* length  = (const int*)d_in[1];
    const float* w_ih0 = (const float*)d_in[2];
    const float* w_hh0 = (const float*)d_in[3];
    const float* b0    = (const float*)d_in[4];
    const float* gih0  = (const float*)d_in[5];
    const float* btih0 = (const float*)d_in[6];
    const float* ghh0  = (const float*)d_in[7];
    const float* bthh0 = (const float*)d_in[8];
    const float* gc0   = (const float*)d_in[9];
    const float* btc0  = (const float*)d_in[10];
    const float* w_ih1 = (const float*)d_in[11];
    const float* w_hh1 = (const float*)d_in[12];
    const float* b1    = (const float*)d_in[13];
    const float* gih1  = (const float*)d_in[14];
    const float* btih1 = (const float*)d_in[15];
    const float* ghh1  = (const float*)d_in[16];
    const float* bthh1 = (const float*)d_in[17];
    const float* gc1   = (const float*)d_in[18];
    const float* btc1  = (const float*)d_in[19];

    float* out = (float*)d_out;
    float* y1 = out;
    float* hn = out + (size_t)TT * BB * HH;
    float* cn = hn + 2 * BB * HH;

    float *p_w0 = nullptr, *p_w1 = nullptr, *p_wI = nullptr;
    cudaGetSymbolAddress((void**)&p_w0, g_wpack0);
    cudaGetSymbolAddress((void**)&p_w1, g_wpack1);
    cudaGetSymbolAddress((void**)&p_wI, g_wpackI);

    const dim3 ggrid(GG / 128, (TT * BB) / 128);
    const int packgrid = (HH * GG) / 256;
    const int initgrid = (BB * HH) / 256;

    // precompute: layer-0 input GEMM + weight packs + state init
    gemm_xw_kernel<<<ggrid, 256>>>(x, w_ih0, DD);
    pack_w_kernel<<<packgrid, 256>>>(w_hh0, p_w0);
    pack_w_kernel<<<packgrid, 256>>>(w_hh1, p_w1);
    pack_w_kernel<<<packgrid, 256>>>(w_ih1, p_wI);
    init_kernel<<<initgrid, 256>>>();

    // 3-role pipelined recurrence
    for (int s = 0; s <= TT + 1; s++)
        lstm_tick_kernel<<<444, 128>>>(s,
                                       ghh0, bthh0, gih0, btih0, b0, gc0, btc0,
                                       ghh1, bthh1, gih1, btih1, b1, gc1, btc1,
                                       length, y1, hn, cn);
}